// round 6
// baseline (speedup 1.0000x reference)
#include <cuda_runtime.h>
#include <math.h>

#define BB    16
#define NN    8400
#define NCLS  80
#define MM    32
#define RMv   16
#define KMAX  10
#define EPSF  1e-7f
#define BN    (BB * NN)
#define TOPB  1024
#define BCEHALF 512            // BCE blocks per branch
#define NV4B  2688000          // BN*NCLS/4 per branch

typedef unsigned long long ull;

// ---------------- scratch (fully rewritten each launch) --------------------------
__device__ float g_bcep[2][BCEHALF];   // BCE softplus partials
__device__ float g_lpart[TOPB][4];     // {bce_t, lbox, ldfl, npos} per assigner block

// ---------------- helpers ---------------------------------------------------------
__device__ __forceinline__ float warpSum(float v) {
#pragma unroll
    for (int o = 16; o > 0; o >>= 1) v += __shfl_down_sync(0xffffffffu, v, o);
    return v;
}
__device__ __forceinline__ ull warpMaxU(ull v) {
#pragma unroll
    for (int o = 16; o > 0; o >>= 1) {
        ull other = __shfl_xor_sync(0xffffffffu, v, o);
        if (other > v) v = other;
    }
    return v;   // butterfly: all lanes hold the max
}

__device__ __constant__ int LS[3]   = {8, 16, 32};
__device__ __constant__ int LG[3]   = {80, 40, 20};
__device__ __constant__ int LOFF[3] = {0, 6400, 8000};

__device__ __forceinline__ void anchor_of(int n, float& ax, float& ay, float& s) {
    int l = (n < 6400) ? 0 : ((n < 8000) ? 1 : 2);
    int g = LG[l], loc = n - LOFF[l];
    int iy = loc / g, ix = loc % g;
    s = (float)LS[l];
    ax = (ix + 0.5f) * s;
    ay = (iy + 0.5f) * s;
}

// index range [i0,i1] with (i+0.5)*s inside [lo,hi]; exact wrt float predicate
__device__ __forceinline__ int2 axis_range(float lo, float hi, float s, int g) {
    int i0 = (int)floorf(lo / s - 0.5f);
    if (i0 < 0) i0 = 0;
    while (i0 < g && (i0 + 0.5f) * s < lo) i0++;
    while (i0 > 0 && ((i0 - 1) + 0.5f) * s >= lo) i0--;
    int i1 = (int)ceilf(hi / s - 0.5f);
    if (i1 > g - 1) i1 = g - 1;
    while (i1 >= 0 && (i1 + 0.5f) * s > hi) i1--;
    while (i1 < g - 1 && ((i1 + 1) + 0.5f) * s <= hi) i1++;
    return make_int2(i0, i1);
}

// decode one anchor's bbox (noinline -> bit-identical at all call sites)
__device__ __noinline__ float4 decode_box(const float* __restrict__ regs, size_t idx,
                                          float ax, float ay, float s) {
    const float4* r4 = (const float4*)(regs + idx * 64);
    float d[4];
#pragma unroll
    for (int g = 0; g < 4; g++) {
        float4 a0 = r4[g * 4 + 0], a1 = r4[g * 4 + 1];
        float4 a2 = r4[g * 4 + 2], a3 = r4[g * 4 + 3];
        float v[16] = { a0.x,a0.y,a0.z,a0.w, a1.x,a1.y,a1.z,a1.w,
                        a2.x,a2.y,a2.z,a2.w, a3.x,a3.y,a3.z,a3.w };
        float mx = v[0];
#pragma unroll
        for (int j = 1; j < 16; j++) mx = fmaxf(mx, v[j]);
        float se = 0.f, sw = 0.f;
#pragma unroll
        for (int j = 0; j < 16; j++) {
            float e = __expf(v[j] - mx);
            se += e; sw += e * (float)j;
        }
        d[g] = sw / se;
    }
    return make_float4(ax - d[0] * s, ay - d[1] * s, ax + d[2] * s, ay + d[3] * s);
}

// align metric (noinline -> bit-identical scan vs argmax)
__device__ __noinline__ float align_fn(float x, float4 p, float ax, float ay, float4 g) {
    float pa = (p.z - p.x) * (p.w - p.y);
    float iw = fmaxf(fminf(p.z, g.z) - fmaxf(p.x, g.x), 0.f);
    float ih = fmaxf(fminf(p.w, g.w) - fmaxf(p.y, g.y), 0.f);
    float inter = iw * ih;
    float ga  = (g.z - g.x) * (g.w - g.y);
    float uni = pa + ga - inter + EPSF;
    float iou = inter / uni;
    float i2 = iou * iou;
    float i6 = i2 * i2 * i2;
    float ing = (ax >= g.x && ax <= g.z && ay >= g.y && ay <= g.w) ? 1.f : 0.f;
    float pdg = 1.f / (1.f + __expf(-x));
    return pdg * i6 * ing;
}

// ---------------- fused kernel: assigner blocks + BCE blocks ----------------------
__global__ __launch_bounds__(256) void fused_kernel(
        const float* __restrict__ cls0, const float* __restrict__ cls1,
        const float* __restrict__ reg0, const float* __restrict__ reg1,
        const int* __restrict__ gl, const float* __restrict__ gb,
        const float* __restrict__ mg) {
    int bid = blockIdx.x, tid = threadIdx.x;
    int lane = tid & 31, wid = tid >> 5;

    // ======================= BCE streaming family =================================
    if (bid >= TOPB) {
        int bid2 = bid - TOPB;
        int brB = bid2 >> 9;          // 0..1
        int i0  = bid2 & 511;
        const float4* c = (const float4*)(brB ? cls1 : cls0);
        float acc = 0.f;
        for (size_t i = (size_t)i0 * 256 + tid; i < (size_t)NV4B;
             i += (size_t)BCEHALF * 256) {
            float4 v = c[i];
            float xs[4] = { v.x, v.y, v.z, v.w };
#pragma unroll
            for (int j = 0; j < 4; j++) {
                float x = xs[j];
                acc += fmaxf(x, 0.f) + __logf(1.f + __expf(-fabsf(x)));
            }
        }
        __shared__ float shr[8];
        float v0 = warpSum(acc);
        if (lane == 0) shr[wid] = v0;
        __syncthreads();
        if (tid < 8) {
            float w0 = shr[tid];
#pragma unroll
            for (int o = 4; o > 0; o >>= 1) w0 += __shfl_down_sync(0xffu, w0, o);
            if (tid == 0) g_bcep[brB][i0] = w0;
        }
        return;
    }

    // ======================= assigner family: block per (br,b,m) ==================
    int br = bid >> 9, bm = bid & 511;
    int b = bm >> 5, m = bm & 31;
    int K = br ? 1 : KMAX;
    const float* cls  = br ? cls1 : cls0;
    const float* regs = br ? reg1 : reg0;

    __shared__ float4 sgt[MM];
    __shared__ int    slab[MM];
    __shared__ ull    wl[8][KMAX];   // per-warp top-10
    __shared__ int    sel[KMAX];

    if (tid < MM) {
        sgt[tid]  = ((const float4*)gb)[b * MM + tid];
        slab[tid] = gl[b * MM + tid];
    }
    __syncthreads();
    float4 gt = sgt[m];
    int    lab = slab[m];

    // rectangle ranges per level (exact in-box index sets)
    int x0[3], y0[3], cw[3], cnt[3], tot = 0;
#pragma unroll
    for (int l = 0; l < 3; l++) {
        float sL = (float)LS[l];
        int2 xr = axis_range(gt.x, gt.z, sL, LG[l]);
        int2 yr = axis_range(gt.y, gt.w, sL, LG[l]);
        int w = xr.y - xr.x + 1; if (w < 0) w = 0;
        int h = yr.y - yr.x + 1; if (h < 0) h = 0;
        x0[l] = xr.x; y0[l] = yr.x; cw[l] = w;
        cnt[l] = w * h; tot += cnt[l];
    }

    ull loc[KMAX];
#pragma unroll
    for (int j = 0; j < KMAX; j++) loc[j] = 0ull;

    // scan rectangle candidates (only place align can be > 0)
    for (int t = tid; t < tot; t += 256) {
        int l = 0, u = t;
        while (u >= cnt[l]) { u -= cnt[l]; l++; }
        int iy = y0[l] + u / cw[l];
        int ix = x0[l] + u % cw[l];
        int n  = LOFF[l] + iy * LG[l] + ix;
        float sL = (float)LS[l];
        float ax = (ix + 0.5f) * sL, ay = (iy + 0.5f) * sL;
        size_t idx = (size_t)b * NN + n;
        float4 p = decode_box(regs, idx, ax, ay, sL);
        float  x = cls[idx * NCLS + lab];
        float  a = align_fn(x, p, ax, ay, gt);
        ull key = ((ull)__float_as_uint(a) << 32) |
                  (ull)(0xFFFFFFFFu - (unsigned)n);
        if (key > loc[KMAX - 1]) {
            loc[KMAX - 1] = key;
#pragma unroll
            for (int j = KMAX - 1; j > 0; j--)
                if (loc[j] > loc[j - 1]) { ull tq = loc[j - 1]; loc[j - 1] = loc[j]; loc[j] = tq; }
        }
    }
    // zero-key baseline: 10 smallest-index anchors NOT in the box (align == 0 exactly)
    if (tid == 0) {
        int got = 0;
        for (int n = 0; n < NN && got < KMAX; n++) {
            float ax, ay, sL;
            anchor_of(n, ax, ay, sL);
            bool in = (ax >= gt.x && ax <= gt.z && ay >= gt.y && ay <= gt.w);
            if (!in) {
                got++;
                ull key = (ull)(0xFFFFFFFFu - (unsigned)n);
                if (key > loc[KMAX - 1]) {
                    loc[KMAX - 1] = key;
#pragma unroll
                    for (int j = KMAX - 1; j > 0; j--)
                        if (loc[j] > loc[j - 1]) { ull tq = loc[j - 1]; loc[j - 1] = loc[j]; loc[j] = tq; }
                }
            }
        }
    }

    // --- warp-local exact merge of 32 sorted lists -> warp top-10 (no syncs) ------
    {
        int ptr = 0;
        ull head = loc[0];
#pragma unroll
        for (int k = 0; k < KMAX; k++) {
            ull win = warpMaxU(head);
            if (lane == 0) wl[wid][k] = win;
            if (head == win && head != 0ull) {
                ptr++;
                head = (ptr < KMAX) ? loc[ptr] : 0ull;
            }
        }
    }
    __syncthreads();

    // --- warp 0: select global top-10 from the 80 warp survivors -------------------
    if (wid == 0) {
        const ull* flat = &wl[0][0];
        ull e0 = flat[lane];
        ull e1 = flat[lane + 32];
        ull e2 = (lane < 16) ? flat[lane + 64] : 0ull;
#pragma unroll
        for (int k = 0; k < KMAX; k++) {
            ull localv = e0;
            if (e1 > localv) localv = e1;
            if (e2 > localv) localv = e2;
            ull win = warpMaxU(localv);
            if      (e0 == win) e0 = 0ull;
            else if (e1 == win) e1 = 0ull;
            else if (e2 == win) e2 = 0ull;
            if (lane == 0) sel[k] = (int)(0xFFFFFFFFu - (unsigned)(win & 0xFFFFFFFFull));
        }
        __syncwarp();

        // --- inline scatter (argmax over m, first occurrence) + loss for winners ---
        float bce = 0.f, lbox = 0.f, ldfl = 0.f, np = 0.f;
        if (lane < K && mg[bm] > 0.f) {
            int n = sel[lane];
            float ax, ay, sL;
            anchor_of(n, ax, ay, sL);
            size_t idx = (size_t)b * NN + n;
            float4 p = decode_box(regs, idx, ax, ay, sL);
            float best = -1.f; int bmx = 0;
#pragma unroll 4
            for (int mp = 0; mp < MM; mp++) {
                float4 g = sgt[mp];
                bool in = (ax >= g.x && ax <= g.z && ay >= g.y && ay <= g.w);
                float a = 0.f;
                if (in) {
                    float x = cls[idx * NCLS + slab[mp]];
                    a = align_fn(x, p, ax, ay, g);
                }
                if (a > best) { best = a; bmx = mp; }
            }
            if (bmx == m) {
                np = 1.f;
                float t1x = gt.x, t1y = gt.y, t2x = gt.z, t2y = gt.w;
                float p1x = p.x, p1y = p.y, p2x = p.z, p2y = p.w;
                float iw = fmaxf(fminf(p2x, t2x) - fmaxf(p1x, t1x), 0.f);
                float ih = fmaxf(fminf(p2y, t2y) - fmaxf(p1y, t1y), 0.f);
                float inter = iw * ih;
                float w1 = p2x - p1x, h1 = p2y - p1y;
                float w2 = t2x - t1x, h2 = t2y - t1y;
                float uni = w1 * h1 + w2 * h2 - inter + EPSF;
                float iou = inter / uni;
                bce = -cls[idx * NCLS + lab] * iou;     // BCE target correction term
                // CIoU (replicates reference bug: ch = max(p2y,t2y) - p1y)
                float cwd = fmaxf(p2x, t2x) - fminf(p1x, t1x);
                float chh = fmaxf(p2y, t2y) - p1y;
                float c2 = cwd * cwd + chh * chh + EPSF;
                float dx = p1x + p2x - t1x - t2x;
                float dy = p1y + p2y - t1y - t2y;
                float rho2 = (dx * dx + dy * dy) * 0.25f;
                const float pi2 = 9.869604401089358f;
                float dv = atanf(w2 / (h2 + EPSF)) - atanf(w1 / (h1 + EPSF));
                float vv = (4.0f / pi2) * dv * dv;
                float alpha = vv / (vv - iou + (1.0f + EPSF));
                lbox = 1.0f - (iou - (rho2 / c2 + vv * alpha));
                // DFL
                float tt[4] = { (ax - t1x) / sL, (ay - t1y) / sL,
                                (t2x - ax) / sL, (t2y - ay) / sL };
                const float* r = regs + idx * 64;
#pragma unroll
                for (int g2 = 0; g2 < 4; g2++) {
                    float v0 = fminf(fmaxf(tt[g2], 0.f), 14.99f);
                    int   tl = (int)v0;
                    float wwl = (float)(tl + 1) - v0;
                    float wwr = 1.0f - wwl;
                    float mx = -1e30f;
#pragma unroll
                    for (int j = 0; j < RMv; j++) mx = fmaxf(mx, r[g2 * RMv + j]);
                    float se = 0.f;
#pragma unroll
                    for (int j = 0; j < RMv; j++) se += __expf(r[g2 * RMv + j] - mx);
                    float lse = __logf(se) + mx;
                    ldfl += -(r[g2 * RMv + tl]     - lse) * wwl
                            -(r[g2 * RMv + tl + 1] - lse) * wwr;
                }
            }
        }
        float vals[4] = { bce, lbox, ldfl, np };
#pragma unroll
        for (int q = 0; q < 4; q++) {
            float v = warpSum(vals[q]);
            if (lane == 0) g_lpart[bid][q] = v;
        }
    }
}

// ---------------- final: warp-per-quantity parallel reduction ----------------------
__global__ void final_kernel(float* __restrict__ out) {
    int tid = threadIdx.x;      // 256 threads, 8 warps
    int lane = tid & 31, wid = tid >> 5;
    __shared__ double sq[10];   // [0]=bce0 [1]=bce1 [2..5]=br0{t,box,dfl,np} [6..9]=br1

    // pass 1: warps 0..7 handle quantities 0..7; pass 2: warps 0..1 handle 8..9
#pragma unroll
    for (int pass = 0; pass < 2; pass++) {
        int q = wid + pass * 8;
        if (q < 10) {
            double acc = 0.0;
            if (q < 2) {
                for (int i = lane; i < BCEHALF; i += 32)
                    acc += (double)g_bcep[q][i];
            } else {
                int brq = (q - 2) >> 2, j = (q - 2) & 3;
                for (int r = lane; r < 512; r += 32)
                    acc += (double)g_lpart[brq * 512 + r][j];
            }
#pragma unroll
            for (int o = 16; o > 0; o >>= 1)
                acc += __shfl_down_sync(0xffffffffu, acc, o);
            if (lane == 0) sq[q] = acc;
        }
    }
    __syncthreads();
    if (tid == 0) {
        double t[2], c[2], bx[2], df[2];
        for (int br = 0; br < 2; br++) {
            double bce  = sq[br] + sq[2 + br * 4 + 0];
            double lbox = sq[2 + br * 4 + 1];
            double ldfl = sq[2 + br * 4 + 2];
            double nfg  = fmax(sq[2 + br * 4 + 3], 1.0);
            c[br]  = bce / nfg;
            bx[br] = lbox / nfg;
            df[br] = ldfl / (nfg * 4.0);
            t[br]  = c[br] + bx[br] * 7.5 + df[br] * 1.5;
        }
        out[0] = (float)(t[0] + t[1]);
        out[1] = (float)(c[0] + c[1]);
        out[2] = (float)(bx[0] + bx[1]);
        out[3] = (float)(df[0] + df[1]);
        out[4] = (float)t[0];
        out[5] = (float)t[1];
    }
}

// ---------------- launch -------------------------------------------------------------
extern "C" void kernel_launch(void* const* d_in, const int* in_sizes, int n_in,
                              void* d_out, int out_size) {
    const float* cls0 = (const float*)d_in[0];
    const float* reg0 = (const float*)d_in[1];
    const float* cls1 = (const float*)d_in[2];
    const float* reg1 = (const float*)d_in[3];
    const int*   gl   = (const int*)d_in[6];
    const float* gb   = (const float*)d_in[7];
    const float* mg   = (const float*)d_in[8];
    float* out = (float*)d_out;

    fused_kernel<<<TOPB + 2 * BCEHALF, 256>>>(cls0, cls1, reg0, reg1, gl, gb, mg);
    final_kernel<<<1, 256>>>(out);
}

// round 7
// speedup vs baseline: 1.1552x; 1.1552x over previous
#include <cuda_runtime.h>
#include <math.h>

#define BB    16
#define NN    8400
#define NCLS  80
#define MM    32
#define RMv   16
#define KMAX  10
#define EPSF  1e-7f
#define BN    (BB * NN)
#define TOPB  1024
#define BCEB  2048
#define NV4B  2688000          // BN*NCLS/4 per branch
#define GRID  (TOPB + BCEB)

typedef unsigned long long ull;

// ---------------- scratch (fully rewritten each launch) --------------------------
__device__ float    g_bcep[2][BCEB];    // BCE softplus partials per BCE block
__device__ float    g_lpart[TOPB][4];   // {bce_t, lbox, ldfl, npos} per assigner block
__device__ unsigned g_ticket = 0;       // last-block-done; reset to 0 by the last block

// ---------------- helpers ---------------------------------------------------------
__device__ __forceinline__ float warpSum(float v) {
#pragma unroll
    for (int o = 16; o > 0; o >>= 1) v += __shfl_down_sync(0xffffffffu, v, o);
    return v;
}

__device__ __constant__ int LS[3]   = {8, 16, 32};
__device__ __constant__ int LG[3]   = {80, 40, 20};
__device__ __constant__ int LOFF[3] = {0, 6400, 8000};

__device__ __forceinline__ void anchor_of(int n, float& ax, float& ay, float& s) {
    int l = (n < 6400) ? 0 : ((n < 8000) ? 1 : 2);
    int g = LG[l], loc = n - LOFF[l];
    int iy = loc / g, ix = loc % g;
    s = (float)LS[l];
    ax = (ix + 0.5f) * s;
    ay = (iy + 0.5f) * s;
}

// index range [i0,i1] with (i+0.5)*s inside [lo,hi]; exact wrt float predicate
__device__ __forceinline__ int2 axis_range(float lo, float hi, float s, int g) {
    int i0 = (int)floorf(lo / s - 0.5f);
    if (i0 < 0) i0 = 0;
    while (i0 < g && (i0 + 0.5f) * s < lo) i0++;
    while (i0 > 0 && ((i0 - 1) + 0.5f) * s >= lo) i0--;
    int i1 = (int)ceilf(hi / s - 0.5f);
    if (i1 > g - 1) i1 = g - 1;
    while (i1 >= 0 && (i1 + 0.5f) * s > hi) i1--;
    while (i1 < g - 1 && ((i1 + 1) + 0.5f) * s <= hi) i1++;
    return make_int2(i0, i1);
}

// decode one anchor's bbox (noinline -> bit-identical at all call sites)
__device__ __noinline__ float4 decode_box(const float* __restrict__ regs, size_t idx,
                                          float ax, float ay, float s) {
    const float4* r4 = (const float4*)(regs + idx * 64);
    float d[4];
#pragma unroll
    for (int g = 0; g < 4; g++) {
        float4 a0 = r4[g * 4 + 0], a1 = r4[g * 4 + 1];
        float4 a2 = r4[g * 4 + 2], a3 = r4[g * 4 + 3];
        float v[16] = { a0.x,a0.y,a0.z,a0.w, a1.x,a1.y,a1.z,a1.w,
                        a2.x,a2.y,a2.z,a2.w, a3.x,a3.y,a3.z,a3.w };
        float mx = v[0];
#pragma unroll
        for (int j = 1; j < 16; j++) mx = fmaxf(mx, v[j]);
        float se = 0.f, sw = 0.f;
#pragma unroll
        for (int j = 0; j < 16; j++) {
            float e = __expf(v[j] - mx);
            se += e; sw += e * (float)j;
        }
        d[g] = sw / se;
    }
    return make_float4(ax - d[0] * s, ay - d[1] * s, ax + d[2] * s, ay + d[3] * s);
}

// align metric (noinline -> bit-identical scan vs argmax)
__device__ __noinline__ float align_fn(float x, float4 p, float ax, float ay, float4 g) {
    float pa = (p.z - p.x) * (p.w - p.y);
    float iw = fmaxf(fminf(p.z, g.z) - fmaxf(p.x, g.x), 0.f);
    float ih = fmaxf(fminf(p.w, g.w) - fmaxf(p.y, g.y), 0.f);
    float inter = iw * ih;
    float ga  = (g.z - g.x) * (g.w - g.y);
    float uni = pa + ga - inter + EPSF;
    float iou = inter / uni;
    float i2 = iou * iou;
    float i6 = i2 * i2 * i2;
    float ing = (ax >= g.x && ax <= g.z && ay >= g.y && ay <= g.w) ? 1.f : 0.f;
    float pdg = 1.f / (1.f + __expf(-x));
    return pdg * i6 * ing;
}

// ---------------- fused kernel: assigner blocks + BCE blocks + last-block final ---
__global__ __launch_bounds__(256) void fused_kernel(
        const float* __restrict__ cls0, const float* __restrict__ cls1,
        const float* __restrict__ reg0, const float* __restrict__ reg1,
        const int* __restrict__ gl, const float* __restrict__ gb,
        const float* __restrict__ mg, float* __restrict__ out) {
    int bid = blockIdx.x, tid = threadIdx.x;
    int lane = tid & 31, wid = tid >> 5;

    __shared__ union {
        struct {
            ull   s[256 * KMAX];
            ull   warpmax[8];
            ull   swin;
            int   sel[KMAX];
            float4 sgt[MM];
            int   slab[MM];
        } a;                     // assigner family
        float shr[8];            // BCE family reduce
        struct { unsigned last; double sq[10]; } f;  // final epilogue
    } sm;

    if (bid >= TOPB) {
        // ======================= BCE streaming family =============================
        int i0 = bid - TOPB;
        const float4* c0 = (const float4*)cls0;
        const float4* c1 = (const float4*)cls1;
        float acc0 = 0.f, acc1 = 0.f;
        for (size_t i = (size_t)i0 * 256 + tid; i < 2 * (size_t)NV4B;
             i += (size_t)BCEB * 256) {
            int b1 = (i >= NV4B);
            float4 v = b1 ? c1[i - NV4B] : c0[i];
            float a = 0.f;
            float xs[4] = { v.x, v.y, v.z, v.w };
#pragma unroll
            for (int j = 0; j < 4; j++) {
                float x = xs[j];
                a += fmaxf(x, 0.f) + __logf(1.f + __expf(-fabsf(x)));
            }
            if (b1) acc1 += a; else acc0 += a;
        }
        float v0 = warpSum(acc0), v1 = warpSum(acc1);
        if (lane == 0) { sm.shr[wid] = v0; }
        __syncthreads();
        if (tid < 8) {
            float w0 = sm.shr[tid];
#pragma unroll
            for (int o = 4; o > 0; o >>= 1) w0 += __shfl_down_sync(0xffu, w0, o);
            if (tid == 0) g_bcep[0][i0] = w0;
        }
        __syncthreads();
        if (lane == 0) { sm.shr[wid] = v1; }
        __syncthreads();
        if (tid < 8) {
            float w1 = sm.shr[tid];
#pragma unroll
            for (int o = 4; o > 0; o >>= 1) w1 += __shfl_down_sync(0xffu, w1, o);
            if (tid == 0) g_bcep[1][i0] = w1;
        }
    } else {
        // ======================= assigner family: block per (br,b,m) ==============
        int br = bid >> 9, bm = bid & 511;
        int b = bm >> 5, m = bm & 31;
        int K = br ? 1 : KMAX;
        const float* cls  = br ? cls1 : cls0;
        const float* regs = br ? reg1 : reg0;

        if (tid < MM) {
            sm.a.sgt[tid]  = ((const float4*)gb)[b * MM + tid];
            sm.a.slab[tid] = gl[b * MM + tid];
        }
        __syncthreads();
        float4 gt = sm.a.sgt[m];
        int    lab = sm.a.slab[m];

        // rectangle ranges per level (exact in-box index sets)
        int x0[3], y0[3], cw[3], cnt[3], tot = 0;
#pragma unroll
        for (int l = 0; l < 3; l++) {
            float sL = (float)LS[l];
            int2 xr = axis_range(gt.x, gt.z, sL, LG[l]);
            int2 yr = axis_range(gt.y, gt.w, sL, LG[l]);
            int w = xr.y - xr.x + 1; if (w < 0) w = 0;
            int h = yr.y - yr.x + 1; if (h < 0) h = 0;
            x0[l] = xr.x; y0[l] = yr.x; cw[l] = w;
            cnt[l] = w * h; tot += cnt[l];
        }

        ull loc[KMAX];
#pragma unroll
        for (int j = 0; j < KMAX; j++) loc[j] = 0ull;

        // scan rectangle candidates (only place align can be > 0)
        for (int t = tid; t < tot; t += 256) {
            int l = 0, u = t;
            while (u >= cnt[l]) { u -= cnt[l]; l++; }
            int iy = y0[l] + u / cw[l];
            int ix = x0[l] + u % cw[l];
            int n  = LOFF[l] + iy * LG[l] + ix;
            float sL = (float)LS[l];
            float ax = (ix + 0.5f) * sL, ay = (iy + 0.5f) * sL;
            size_t idx = (size_t)b * NN + n;
            float4 p = decode_box(regs, idx, ax, ay, sL);
            float  x = cls[idx * NCLS + lab];
            float  a = align_fn(x, p, ax, ay, gt);
            ull key = ((ull)__float_as_uint(a) << 32) |
                      (ull)(0xFFFFFFFFu - (unsigned)n);
            if (key > loc[KMAX - 1]) {
                loc[KMAX - 1] = key;
#pragma unroll
                for (int j = KMAX - 1; j > 0; j--)
                    if (loc[j] > loc[j - 1]) { ull tq = loc[j - 1]; loc[j - 1] = loc[j]; loc[j] = tq; }
            }
        }
        // zero-key baseline: 10 smallest-index anchors NOT in the box
        if (tid == 0) {
            int got = 0;
            for (int n = 0; n < NN && got < KMAX; n++) {
                float ax, ay, sL;
                anchor_of(n, ax, ay, sL);
                bool in = (ax >= gt.x && ax <= gt.z && ay >= gt.y && ay <= gt.w);
                if (!in) {
                    got++;
                    ull key = (ull)(0xFFFFFFFFu - (unsigned)n);
                    if (key > loc[KMAX - 1]) {
                        loc[KMAX - 1] = key;
#pragma unroll
                        for (int j = KMAX - 1; j > 0; j--)
                            if (loc[j] > loc[j - 1]) { ull tq = loc[j - 1]; loc[j - 1] = loc[j]; loc[j] = tq; }
                    }
                }
            }
        }

        // block tournament merge -> sel[0..K-1]
#pragma unroll
        for (int j = 0; j < KMAX; j++) sm.a.s[tid * KMAX + j] = loc[j];
        __syncthreads();
        int ptr = 0;
        for (int k = 0; k < K; k++) {
            ull h = (ptr < KMAX) ? sm.a.s[tid * KMAX + ptr] : 0ull;
            ull w = h;
#pragma unroll
            for (int o = 16; o > 0; o >>= 1) {
                ull other = __shfl_down_sync(0xffffffffu, w, o);
                if (other > w) w = other;
            }
            if (lane == 0) sm.a.warpmax[wid] = w;
            __syncthreads();
            if (tid < 8) {
                ull v = sm.a.warpmax[tid];
#pragma unroll
                for (int o = 4; o > 0; o >>= 1) {
                    ull other = __shfl_down_sync(0xffu, v, o);
                    if (other > v) v = other;
                }
                if (tid == 0) sm.a.swin = v;
            }
            __syncthreads();
            ull win = sm.a.swin;
            if (h == win && h != 0ull) ptr++;
            if (tid == 0) sm.a.sel[k] = (int)(0xFFFFFFFFu - (unsigned)(win & 0xFFFFFFFFull));
            __syncthreads();
        }

        // inline scatter (argmax over m, first occurrence) + loss for winners
        float bce = 0.f, lbox = 0.f, ldfl = 0.f, np = 0.f;
        if (tid < K && mg[bm] > 0.f) {
            int n = sm.a.sel[tid];
            float ax, ay, sL;
            anchor_of(n, ax, ay, sL);
            size_t idx = (size_t)b * NN + n;
            float4 p = decode_box(regs, idx, ax, ay, sL);
            float best = -1.f; int bmx = 0;
#pragma unroll 4
            for (int mp = 0; mp < MM; mp++) {
                float4 g = sm.a.sgt[mp];
                bool in = (ax >= g.x && ax <= g.z && ay >= g.y && ay <= g.w);
                float a = 0.f;
                if (in) {
                    float x = cls[idx * NCLS + sm.a.slab[mp]];
                    a = align_fn(x, p, ax, ay, g);
                }
                if (a > best) { best = a; bmx = mp; }
            }
            if (bmx == m) {
                np = 1.f;
                float t1x = gt.x, t1y = gt.y, t2x = gt.z, t2y = gt.w;
                float p1x = p.x, p1y = p.y, p2x = p.z, p2y = p.w;
                float iw = fmaxf(fminf(p2x, t2x) - fmaxf(p1x, t1x), 0.f);
                float ih = fmaxf(fminf(p2y, t2y) - fmaxf(p1y, t1y), 0.f);
                float inter = iw * ih;
                float w1 = p2x - p1x, h1 = p2y - p1y;
                float w2 = t2x - t1x, h2 = t2y - t1y;
                float uni = w1 * h1 + w2 * h2 - inter + EPSF;
                float iou = inter / uni;
                bce = -cls[idx * NCLS + lab] * iou;     // BCE target correction term
                // CIoU (replicates reference bug: ch = max(p2y,t2y) - p1y)
                float cwd = fmaxf(p2x, t2x) - fminf(p1x, t1x);
                float chh = fmaxf(p2y, t2y) - p1y;
                float c2 = cwd * cwd + chh * chh + EPSF;
                float dx = p1x + p2x - t1x - t2x;
                float dy = p1y + p2y - t1y - t2y;
                float rho2 = (dx * dx + dy * dy) * 0.25f;
                const float pi2 = 9.869604401089358f;
                float dv = atanf(w2 / (h2 + EPSF)) - atanf(w1 / (h1 + EPSF));
                float vv = (4.0f / pi2) * dv * dv;
                float alpha = vv / (vv - iou + (1.0f + EPSF));
                lbox = 1.0f - (iou - (rho2 / c2 + vv * alpha));
                // DFL
                float tt[4] = { (ax - t1x) / sL, (ay - t1y) / sL,
                                (t2x - ax) / sL, (t2y - ay) / sL };
                const float* r = regs + idx * 64;
#pragma unroll
                for (int g2 = 0; g2 < 4; g2++) {
                    float v0 = fminf(fmaxf(tt[g2], 0.f), 14.99f);
                    int   tl = (int)v0;
                    float wwl = (float)(tl + 1) - v0;
                    float wwr = 1.0f - wwl;
                    float mx = -1e30f;
#pragma unroll
                    for (int j = 0; j < RMv; j++) mx = fmaxf(mx, r[g2 * RMv + j]);
                    float se = 0.f;
#pragma unroll
                    for (int j = 0; j < RMv; j++) se += __expf(r[g2 * RMv + j] - mx);
                    float lse = __logf(se) + mx;
                    ldfl += -(r[g2 * RMv + tl]     - lse) * wwl
                            -(r[g2 * RMv + tl + 1] - lse) * wwr;
                }
            }
        }
        // winners live only in warp 0 (K <= 10)
        if (wid == 0) {
            float vals[4] = { bce, lbox, ldfl, np };
#pragma unroll
            for (int q = 0; q < 4; q++) {
                float v = warpSum(vals[q]);
                if (lane == 0) g_lpart[bid][q] = v;
            }
        }
        __syncthreads();
    }

    // ======================= last-block final reduction ============================
    __threadfence();
    if (tid == 0) sm.f.last = (atomicAdd(&g_ticket, 1u) == GRID - 1);
    __syncthreads();
    if (!sm.f.last) return;

    // this is the last block; all partials are globally visible
#pragma unroll
    for (int pass = 0; pass < 2; pass++) {
        int q = wid + pass * 8;
        if (q < 10) {
            double acc = 0.0;
            if (q < 2) {
                for (int i = lane; i < BCEB; i += 32)
                    acc += (double)g_bcep[q][i];
            } else {
                int brq = (q - 2) >> 2, j = (q - 2) & 3;
                for (int r2 = lane; r2 < 512; r2 += 32)
                    acc += (double)g_lpart[brq * 512 + r2][j];
            }
#pragma unroll
            for (int o = 16; o > 0; o >>= 1)
                acc += __shfl_down_sync(0xffffffffu, acc, o);
            if (lane == 0) sm.f.sq[q] = acc;
        }
    }
    __syncthreads();
    if (tid == 0) {
        g_ticket = 0;    // reset for next graph replay
        double t[2], c[2], bx[2], df[2];
        for (int br2 = 0; br2 < 2; br2++) {
            double bce  = sm.f.sq[br2] + sm.f.sq[2 + br2 * 4 + 0];
            double lbox = sm.f.sq[2 + br2 * 4 + 1];
            double ldfl = sm.f.sq[2 + br2 * 4 + 2];
            double nfg  = fmax(sm.f.sq[2 + br2 * 4 + 3], 1.0);
            c[br2]  = bce / nfg;
            bx[br2] = lbox / nfg;
            df[br2] = ldfl / (nfg * 4.0);
            t[br2]  = c[br2] + bx[br2] * 7.5 + df[br2] * 1.5;
        }
        out[0] = (float)(t[0] + t[1]);
        out[1] = (float)(c[0] + c[1]);
        out[2] = (float)(bx[0] + bx[1]);
        out[3] = (float)(df[0] + df[1]);
        out[4] = (float)t[0];
        out[5] = (float)t[1];
    }
}

// ---------------- launch -------------------------------------------------------------
extern "C" void kernel_launch(void* const* d_in, const int* in_sizes, int n_in,
                              void* d_out, int out_size) {
    const float* cls0 = (const float*)d_in[0];
    const float* reg0 = (const float*)d_in[1];
    const float* cls1 = (const float*)d_in[2];
    const float* reg1 = (const float*)d_in[3];
    const int*   gl   = (const int*)d_in[6];
    const float* gb   = (const float*)d_in[7];
    const float* mg   = (const float*)d_in[8];
    float* out = (float*)d_out;

    fused_kernel<<<GRID, 256>>>(cls0, cls1, reg0, reg1, gl, gb, mg, out);
}

// round 8
// speedup vs baseline: 1.4822x; 1.2831x over previous
#include <cuda_runtime.h>
#include <math.h>

#define BB    16
#define NN    8400
#define NCLS  80
#define MM    32
#define RMv   16
#define KMAX  10
#define EPSF  1e-7f
#define BN    (BB * NN)
#define TOPB  1024
#define BCEB  2100             // 2100 * 2560 = 2 * NV4B exactly
#define BCEHALF 1050
#define F4PB  2560             // float4 per BCE block
#define NV4B  2688000          // BN*NCLS/4 per branch
#define GRID  (TOPB + BCEB)

typedef unsigned long long ull;

// ---------------- scratch (fully rewritten each launch) --------------------------
__device__ float    g_bcep[BCEB];       // BCE partial per BCE block (branch by range)
__device__ float    g_lpart[TOPB][4];   // {bce_t, lbox, ldfl, npos} per assigner block
__device__ unsigned g_ticket = 0;       // last-block-done; reset by the last block

// ---------------- helpers ---------------------------------------------------------
__device__ __forceinline__ float warpSum(float v) {
#pragma unroll
    for (int o = 16; o > 0; o >>= 1) v += __shfl_down_sync(0xffffffffu, v, o);
    return v;
}

__device__ __constant__ int LS[3]   = {8, 16, 32};
__device__ __constant__ int LG[3]   = {80, 40, 20};
__device__ __constant__ int LOFF[3] = {0, 6400, 8000};

__device__ __forceinline__ void anchor_of(int n, float& ax, float& ay, float& s) {
    int l = (n < 6400) ? 0 : ((n < 8000) ? 1 : 2);
    int g = LG[l], loc = n - LOFF[l];
    int iy = loc / g, ix = loc % g;
    s = (float)LS[l];
    ax = (ix + 0.5f) * s;
    ay = (iy + 0.5f) * s;
}

// index range [i0,i1] with (i+0.5)*s inside [lo,hi]; exact wrt float predicate
__device__ __forceinline__ int2 axis_range(float lo, float hi, float s, int g) {
    int i0 = (int)floorf(lo / s - 0.5f);
    if (i0 < 0) i0 = 0;
    while (i0 < g && (i0 + 0.5f) * s < lo) i0++;
    while (i0 > 0 && ((i0 - 1) + 0.5f) * s >= lo) i0--;
    int i1 = (int)ceilf(hi / s - 0.5f);
    if (i1 > g - 1) i1 = g - 1;
    while (i1 >= 0 && (i1 + 0.5f) * s > hi) i1--;
    while (i1 < g - 1 && ((i1 + 1) + 0.5f) * s <= hi) i1++;
    return make_int2(i0, i1);
}

// decode one anchor's bbox (noinline -> bit-identical at all call sites)
__device__ __noinline__ float4 decode_box(const float* __restrict__ regs, size_t idx,
                                          float ax, float ay, float s) {
    const float4* r4 = (const float4*)(regs + idx * 64);
    float d[4];
#pragma unroll
    for (int g = 0; g < 4; g++) {
        float4 a0 = r4[g * 4 + 0], a1 = r4[g * 4 + 1];
        float4 a2 = r4[g * 4 + 2], a3 = r4[g * 4 + 3];
        float v[16] = { a0.x,a0.y,a0.z,a0.w, a1.x,a1.y,a1.z,a1.w,
                        a2.x,a2.y,a2.z,a2.w, a3.x,a3.y,a3.z,a3.w };
        float mx = v[0];
#pragma unroll
        for (int j = 1; j < 16; j++) mx = fmaxf(mx, v[j]);
        float se = 0.f, sw = 0.f;
#pragma unroll
        for (int j = 0; j < 16; j++) {
            float e = __expf(v[j] - mx);
            se += e; sw += e * (float)j;
        }
        d[g] = sw / se;
    }
    return make_float4(ax - d[0] * s, ay - d[1] * s, ax + d[2] * s, ay + d[3] * s);
}

// align metric (noinline -> bit-identical scan vs argmax)
__device__ __noinline__ float align_fn(float x, float4 p, float ax, float ay, float4 g) {
    float pa = (p.z - p.x) * (p.w - p.y);
    float iw = fmaxf(fminf(p.z, g.z) - fmaxf(p.x, g.x), 0.f);
    float ih = fmaxf(fminf(p.w, g.w) - fmaxf(p.y, g.y), 0.f);
    float inter = iw * ih;
    float ga  = (g.z - g.x) * (g.w - g.y);
    float uni = pa + ga - inter + EPSF;
    float iou = inter / uni;
    float i2 = iou * iou;
    float i6 = i2 * i2 * i2;
    float ing = (ax >= g.x && ax <= g.z && ay >= g.y && ay <= g.w) ? 1.f : 0.f;
    float pdg = 1.f / (1.f + __expf(-x));
    return pdg * i6 * ing;
}

// ---------------- fused kernel: assigner blocks + BCE blocks + last-block final ---
__global__ __launch_bounds__(256) void fused_kernel(
        const float* __restrict__ cls0, const float* __restrict__ cls1,
        const float* __restrict__ reg0, const float* __restrict__ reg1,
        const int* __restrict__ gl, const float* __restrict__ gb,
        const float* __restrict__ mg, float* __restrict__ out) {
    int bid = blockIdx.x, tid = threadIdx.x;
    int lane = tid & 31, wid = tid >> 5;

    __shared__ union {
        struct {
            ull   s[256 * KMAX];
            ull   warpmax[8];
            ull   swin;
            int   sel[KMAX];
            float4 sgt[MM];
            int   slab[MM];
        } a;                     // assigner family
        float shr[8];            // BCE family reduce
        struct { unsigned last; double sq[10]; } f;  // final epilogue
    } sm;

    if (bid >= TOPB) {
        // ======================= BCE streaming family (MLP-batched) ===============
        int i0  = bid - TOPB;                    // 0..2099
        int brB = (i0 >= BCEHALF);
        const float4* c = (const float4*)(brB ? cls1 : cls0);
        size_t base = (size_t)(i0 - (brB ? BCEHALF : 0)) * F4PB + tid;
        float acc = 0.f;
#pragma unroll
        for (int half = 0; half < 2; half++) {
            float4 v[5];
#pragma unroll
            for (int j = 0; j < 5; j++)
                v[j] = c[base + (size_t)(half * 5 + j) * 256];
            float prod = 1.f;
#pragma unroll
            for (int j = 0; j < 5; j++) {
                float xs[4] = { v[j].x, v[j].y, v[j].z, v[j].w };
#pragma unroll
                for (int e = 0; e < 4; e++) {
                    float x = xs[e];
                    acc  += fmaxf(x, 0.f);
                    prod *= 1.f + __expf(-fabsf(x));
                }
                if (j == 1 || j == 3) { acc += __logf(prod); prod = 1.f; }
            }
            acc += __logf(prod);
        }
        float v0 = warpSum(acc);
        if (lane == 0) sm.shr[wid] = v0;
        __syncthreads();
        if (tid < 8) {
            float w0 = sm.shr[tid];
#pragma unroll
            for (int o = 4; o > 0; o >>= 1) w0 += __shfl_down_sync(0xffu, w0, o);
            if (tid == 0) g_bcep[i0] = w0;
        }
    } else {
        // ======================= assigner family: block per (br,b,m) ==============
        int br = bid >> 9, bm = bid & 511;
        int b = bm >> 5, m = bm & 31;
        int K = br ? 1 : KMAX;
        const float* cls  = br ? cls1 : cls0;
        const float* regs = br ? reg1 : reg0;

        if (tid < MM) {
            sm.a.sgt[tid]  = ((const float4*)gb)[b * MM + tid];
            sm.a.slab[tid] = gl[b * MM + tid];
        }
        __syncthreads();
        float4 gt = sm.a.sgt[m];
        int    lab = sm.a.slab[m];

        // rectangle ranges per level (exact in-box index sets)
        int x0[3], y0[3], cw[3], cnt[3], tot = 0;
#pragma unroll
        for (int l = 0; l < 3; l++) {
            float sL = (float)LS[l];
            int2 xr = axis_range(gt.x, gt.z, sL, LG[l]);
            int2 yr = axis_range(gt.y, gt.w, sL, LG[l]);
            int w = xr.y - xr.x + 1; if (w < 0) w = 0;
            int h = yr.y - yr.x + 1; if (h < 0) h = 0;
            x0[l] = xr.x; y0[l] = yr.x; cw[l] = w;
            cnt[l] = w * h; tot += cnt[l];
        }

        ull loc[KMAX];
#pragma unroll
        for (int j = 0; j < KMAX; j++) loc[j] = 0ull;

        // scan rectangle candidates (only place align can be > 0)
        for (int t = tid; t < tot; t += 256) {
            int l = 0, u = t;
            while (u >= cnt[l]) { u -= cnt[l]; l++; }
            int iy = y0[l] + u / cw[l];
            int ix = x0[l] + u % cw[l];
            int n  = LOFF[l] + iy * LG[l] + ix;
            float sL = (float)LS[l];
            float ax = (ix + 0.5f) * sL, ay = (iy + 0.5f) * sL;
            size_t idx = (size_t)b * NN + n;
            float4 p = decode_box(regs, idx, ax, ay, sL);
            float  x = cls[idx * NCLS + lab];
            float  a = align_fn(x, p, ax, ay, gt);
            ull key = ((ull)__float_as_uint(a) << 32) |
                      (ull)(0xFFFFFFFFu - (unsigned)n);
            if (key > loc[KMAX - 1]) {
                loc[KMAX - 1] = key;
#pragma unroll
                for (int j = KMAX - 1; j > 0; j--)
                    if (loc[j] > loc[j - 1]) { ull tq = loc[j - 1]; loc[j - 1] = loc[j]; loc[j] = tq; }
            }
        }
        // zero-key baseline: 10 smallest-index anchors NOT in the box
        if (tid == 0) {
            int got = 0;
            for (int n = 0; n < NN && got < KMAX; n++) {
                float ax, ay, sL;
                anchor_of(n, ax, ay, sL);
                bool in = (ax >= gt.x && ax <= gt.z && ay >= gt.y && ay <= gt.w);
                if (!in) {
                    got++;
                    ull key = (ull)(0xFFFFFFFFu - (unsigned)n);
                    if (key > loc[KMAX - 1]) {
                        loc[KMAX - 1] = key;
#pragma unroll
                        for (int j = KMAX - 1; j > 0; j--)
                            if (loc[j] > loc[j - 1]) { ull tq = loc[j - 1]; loc[j - 1] = loc[j]; loc[j] = tq; }
                    }
                }
            }
        }

        // block tournament merge -> sel[0..K-1]
#pragma unroll
        for (int j = 0; j < KMAX; j++) sm.a.s[tid * KMAX + j] = loc[j];
        __syncthreads();
        int ptr = 0;
        for (int k = 0; k < K; k++) {
            ull h = (ptr < KMAX) ? sm.a.s[tid * KMAX + ptr] : 0ull;
            ull w = h;
#pragma unroll
            for (int o = 16; o > 0; o >>= 1) {
                ull other = __shfl_down_sync(0xffffffffu, w, o);
                if (other > w) w = other;
            }
            if (lane == 0) sm.a.warpmax[wid] = w;
            __syncthreads();
            if (tid < 8) {
                ull v = sm.a.warpmax[tid];
#pragma unroll
                for (int o = 4; o > 0; o >>= 1) {
                    ull other = __shfl_down_sync(0xffu, v, o);
                    if (other > v) v = other;
                }
                if (tid == 0) sm.a.swin = v;
            }
            __syncthreads();
            ull win = sm.a.swin;
            if (h == win && h != 0ull) ptr++;
            if (tid == 0) sm.a.sel[k] = (int)(0xFFFFFFFFu - (unsigned)(win & 0xFFFFFFFFull));
            __syncthreads();
        }

        // inline scatter (argmax over m, first occurrence) + loss for winners
        float bce = 0.f, lbox = 0.f, ldfl = 0.f, np = 0.f;
        if (tid < K && mg[bm] > 0.f) {
            int n = sm.a.sel[tid];
            float ax, ay, sL;
            anchor_of(n, ax, ay, sL);
            size_t idx = (size_t)b * NN + n;
            float4 p = decode_box(regs, idx, ax, ay, sL);
            float best = -1.f; int bmx = 0;
#pragma unroll 4
            for (int mp = 0; mp < MM; mp++) {
                float4 g = sm.a.sgt[mp];
                bool in = (ax >= g.x && ax <= g.z && ay >= g.y && ay <= g.w);
                float a = 0.f;
                if (in) {
                    float x = cls[idx * NCLS + sm.a.slab[mp]];
                    a = align_fn(x, p, ax, ay, g);
                }
                if (a > best) { best = a; bmx = mp; }
            }
            if (bmx == m) {
                np = 1.f;
                float t1x = gt.x, t1y = gt.y, t2x = gt.z, t2y = gt.w;
                float p1x = p.x, p1y = p.y, p2x = p.z, p2y = p.w;
                float iw = fmaxf(fminf(p2x, t2x) - fmaxf(p1x, t1x), 0.f);
                float ih = fmaxf(fminf(p2y, t2y) - fmaxf(p1y, t1y), 0.f);
                float inter = iw * ih;
                float w1 = p2x - p1x, h1 = p2y - p1y;
                float w2 = t2x - t1x, h2 = t2y - t1y;
                float uni = w1 * h1 + w2 * h2 - inter + EPSF;
                float iou = inter / uni;
                bce = -cls[idx * NCLS + lab] * iou;     // BCE target correction term
                // CIoU (replicates reference bug: ch = max(p2y,t2y) - p1y)
                float cwd = fmaxf(p2x, t2x) - fminf(p1x, t1x);
                float chh = fmaxf(p2y, t2y) - p1y;
                float c2 = cwd * cwd + chh * chh + EPSF;
                float dx = p1x + p2x - t1x - t2x;
                float dy = p1y + p2y - t1y - t2y;
                float rho2 = (dx * dx + dy * dy) * 0.25f;
                const float pi2 = 9.869604401089358f;
                float dv = atanf(w2 / (h2 + EPSF)) - atanf(w1 / (h1 + EPSF));
                float vv = (4.0f / pi2) * dv * dv;
                float alpha = vv / (vv - iou + (1.0f + EPSF));
                lbox = 1.0f - (iou - (rho2 / c2 + vv * alpha));
                // DFL
                float tt[4] = { (ax - t1x) / sL, (ay - t1y) / sL,
                                (t2x - ax) / sL, (t2y - ay) / sL };
                const float* r = regs + idx * 64;
#pragma unroll
                for (int g2 = 0; g2 < 4; g2++) {
                    float v0 = fminf(fmaxf(tt[g2], 0.f), 14.99f);
                    int   tl = (int)v0;
                    float wwl = (float)(tl + 1) - v0;
                    float wwr = 1.0f - wwl;
                    float mx = -1e30f;
#pragma unroll
                    for (int j = 0; j < RMv; j++) mx = fmaxf(mx, r[g2 * RMv + j]);
                    float se = 0.f;
#pragma unroll
                    for (int j = 0; j < RMv; j++) se += __expf(r[g2 * RMv + j] - mx);
                    float lse = __logf(se) + mx;
                    ldfl += -(r[g2 * RMv + tl]     - lse) * wwl
                            -(r[g2 * RMv + tl + 1] - lse) * wwr;
                }
            }
        }
        // winners live only in warp 0 (K <= 10)
        if (wid == 0) {
            float vals[4] = { bce, lbox, ldfl, np };
#pragma unroll
            for (int q = 0; q < 4; q++) {
                float v = warpSum(vals[q]);
                if (lane == 0) g_lpart[bid][q] = v;
            }
        }
        __syncthreads();
    }

    // ======================= last-block final reduction ============================
    __threadfence();
    if (tid == 0) sm.f.last = (atomicAdd(&g_ticket, 1u) == GRID - 1);
    __syncthreads();
    if (!sm.f.last) return;

    // this is the last block; all partials are globally visible
#pragma unroll
    for (int pass = 0; pass < 2; pass++) {
        int q = wid + pass * 8;
        if (q < 10) {
            double acc = 0.0;
            if (q < 2) {
                for (int i = lane; i < BCEHALF; i += 32)
                    acc += (double)g_bcep[q * BCEHALF + i];
            } else {
                int brq = (q - 2) >> 2, j = (q - 2) & 3;
                for (int r2 = lane; r2 < 512; r2 += 32)
                    acc += (double)g_lpart[brq * 512 + r2][j];
            }
#pragma unroll
            for (int o = 16; o > 0; o >>= 1)
                acc += __shfl_down_sync(0xffffffffu, acc, o);
            if (lane == 0) sm.f.sq[q] = acc;
        }
    }
    __syncthreads();
    if (tid == 0) {
        g_ticket = 0;    // reset for next graph replay
        double t[2], c[2], bx[2], df[2];
        for (int br2 = 0; br2 < 2; br2++) {
            double bce  = sm.f.sq[br2] + sm.f.sq[2 + br2 * 4 + 0];
            double lbox = sm.f.sq[2 + br2 * 4 + 1];
            double ldfl = sm.f.sq[2 + br2 * 4 + 2];
            double nfg  = fmax(sm.f.sq[2 + br2 * 4 + 3], 1.0);
            c[br2]  = bce / nfg;
            bx[br2] = lbox / nfg;
            df[br2] = ldfl / (nfg * 4.0);
            t[br2]  = c[br2] + bx[br2] * 7.5 + df[br2] * 1.5;
        }
        out[0] = (float)(t[0] + t[1]);
        out[1] = (float)(c[0] + c[1]);
        out[2] = (float)(bx[0] + bx[1]);
        out[3] = (float)(df[0] + df[1]);
        out[4] = (float)t[0];
        out[5] = (float)t[1];
    }
}

// ---------------- launch -------------------------------------------------------------
extern "C" void kernel_launch(void* const* d_in, const int* in_sizes, int n_in,
                              void* d_out, int out_size) {
    const float* cls0 = (const float*)d_in[0];
    const float* reg0 = (const float*)d_in[1];
    const float* cls1 = (const float*)d_in[2];
    const float* reg1 = (const float*)d_in[3];
    const int*   gl   = (const int*)d_in[6];
    const float* gb   = (const float*)d_in[7];
    const float* mg   = (const float*)d_in[8];
    float* out = (float*)d_out;

    fused_kernel<<<GRID, 256>>>(cls0, cls1, reg0, reg1, gl, gb, mg, out);
}